// round 16
// baseline (speedup 1.0000x reference)
#include <cuda_runtime.h>
#include <cuda_bf16.h>
#include <math.h>
#include <stdint.h>

#define B 64
#define F 32

typedef unsigned long long u64;

__device__ __align__(128) float g_f128[(size_t)B * F * 128 * 128];
__device__ __align__(128) float g_bufA[(size_t)B * F * 64 * 64];
__device__ __align__(128) float g_bufB[(size_t)B * F * 64 * 64];
__device__ __align__(128) float g_bufC[(size_t)B * F * 64 * 64];
__device__ __align__(128) float g_bufD[(size_t)B * F * 64 * 64];
__device__ float g_mean[B * F];
__device__ float g_rstd[B * F];

// ---------------------------------------------------------------------------
// Packed f32x2 helpers (FFMA2 SIMT kernels)
// ---------------------------------------------------------------------------
__device__ __forceinline__ u64 pack2(float v) {
    u64 r; asm("mov.b64 %0, {%1, %1};" : "=l"(r) : "f"(v)); return r;
}
__device__ __forceinline__ void fma2(u64& acc, u64 a, u64 b) {
    asm("fma.rn.f32x2 %0, %1, %2, %0;" : "+l"(acc) : "l"(a), "l"(b));
}
__device__ __forceinline__ float2 unpack2(u64 v) {
    float2 r; asm("mov.b64 {%0, %1}, %2;" : "=f"(r.x), "=f"(r.y) : "l"(v)); return r;
}

// ---------------------------------------------------------------------------
// tf32 helpers (legacy mma.sync path, works on plain sm_103 target)
// ---------------------------------------------------------------------------
__device__ __forceinline__ uint32_t f2tf32(float f) {
    uint32_t r; asm("cvt.rna.tf32.f32 %0, %1;" : "=r"(r) : "f"(f)); return r;
}
__device__ __forceinline__ void mma_tf32(float* d, const uint32_t* a, uint32_t b0, uint32_t b1) {
    asm volatile(
        "mma.sync.aligned.m16n8k8.row.col.f32.tf32.tf32.f32 "
        "{%0,%1,%2,%3}, {%4,%5,%6,%7}, {%8,%9}, {%0,%1,%2,%3};"
        : "+f"(d[0]), "+f"(d[1]), "+f"(d[2]), "+f"(d[3])
        : "r"(a[0]), "r"(a[1]), "r"(a[2]), "r"(a[3]), "r"(b0), "r"(b1));
}

// ---------------------------------------------------------------------------
// Instance-norm statistics
// ---------------------------------------------------------------------------
__global__ void in_stats_kernel(const float* __restrict__ in, int HW,
                                float* __restrict__ mean, float* __restrict__ rstd)
{
    int bc = blockIdx.x;
    const float4* p = (const float4*)(in + (size_t)bc * HW);
    int n4 = HW >> 2;
    float s1 = 0.f, s2 = 0.f;
    for (int i = threadIdx.x; i < n4; i += blockDim.x) {
        float4 v = p[i];
        s1 += v.x + v.y + v.z + v.w;
        s2 += v.x * v.x + v.y * v.y + v.z * v.z + v.w * v.w;
    }
    __shared__ float sh1[32], sh2[32];
    #pragma unroll
    for (int o = 16; o; o >>= 1) {
        s1 += __shfl_down_sync(0xffffffffu, s1, o);
        s2 += __shfl_down_sync(0xffffffffu, s2, o);
    }
    int lane = threadIdx.x & 31, w = threadIdx.x >> 5;
    if (lane == 0) { sh1[w] = s1; sh2[w] = s2; }
    __syncthreads();
    if (w == 0) {
        int nw = blockDim.x >> 5;
        s1 = lane < nw ? sh1[lane] : 0.f;
        s2 = lane < nw ? sh2[lane] : 0.f;
        #pragma unroll
        for (int o = 16; o; o >>= 1) {
            s1 += __shfl_down_sync(0xffffffffu, s1, o);
            s2 += __shfl_down_sync(0xffffffffu, s2, o);
        }
        if (lane == 0) {
            float m = s1 / (float)HW;
            float var = s2 / (float)HW - m * m;
            mean[bc] = m;
            rstd[bc] = rsqrtf(var + 1e-5f);
        }
    }
}

// ---------------------------------------------------------------------------
// conv1: 7x7 s2 p3 (round-10 proven)
// ---------------------------------------------------------------------------
__global__ void conv1_kernel(const float* __restrict__ x,
                             const float* __restrict__ w,
                             const float* __restrict__ bias,
                             const float* __restrict__ mean,
                             const float* __restrict__ rstd,
                             float* __restrict__ out)
{
    __shared__ __align__(16) float s_w[147][32];
    __shared__ __align__(16) float s_in[3][37][38];
    int b = blockIdx.z;
    int oh0 = blockIdx.y * 16, ow0 = blockIdx.x * 16;
    int tid = threadIdx.x;

    for (int i = tid; i < 32 * 147; i += 256) {
        int f = i / 147, ck = i - f * 147;
        s_w[ck][f] = w[i];
    }
    int ih0 = oh0 * 2 - 3, iw0 = ow0 * 2 - 3;
    for (int c = 0; c < 3; c++) {
        int bc = b * 3 + c;
        float m = mean[bc], r = rstd[bc];
        const float* xp = x + (size_t)bc * 65536;
        for (int i = tid; i < 37 * 37; i += 256) {
            int rr = i / 37, cc = i - rr * 37;
            int ih = ih0 + rr, iw = iw0 + cc;
            float v = 0.f;
            if ((unsigned)ih < 256u && (unsigned)iw < 256u)
                v = (xp[ih * 256 + iw] - m) * r;
            s_in[c][rr][cc] = v;
        }
    }
    __syncthreads();

    const int fg = tid >> 6;
    const int pg = tid & 63;
    const int prow = pg >> 2;
    const int pc0 = (pg & 3) * 4;
    const int f0 = fg * 8;

    u64 acc2[4][4];
    #pragma unroll
    for (int p = 0; p < 4; p++)
        #pragma unroll
        for (int q = 0; q < 4; q++) acc2[p][q] = 0ull;

    for (int c = 0; c < 3; c++) {
        #pragma unroll 1
        for (int kh = 0; kh < 7; kh++) {
            const float* rowp = &s_in[c][prow * 2 + kh][pc0 * 2];
            u64 rv2[13];
            #pragma unroll
            for (int i = 0; i < 13; i++) rv2[i] = pack2(rowp[i]);
            #pragma unroll
            for (int kw = 0; kw < 7; kw++) {
                const u64* wp = (const u64*)&s_w[c * 49 + kh * 7 + kw][f0];
                u64 w0 = wp[0], w1 = wp[1], w2 = wp[2], w3 = wp[3];
                #pragma unroll
                for (int p = 0; p < 4; p++) {
                    u64 vv = rv2[2 * p + kw];
                    fma2(acc2[p][0], vv, w0);
                    fma2(acc2[p][1], vv, w1);
                    fma2(acc2[p][2], vv, w2);
                    fma2(acc2[p][3], vv, w3);
                }
            }
        }
    }
    int oh = oh0 + prow;
    int owb = ow0 + pc0;
    #pragma unroll
    for (int q = 0; q < 4; q++) {
        float2 u0 = unpack2(acc2[0][q]), u1 = unpack2(acc2[1][q]);
        float2 u2 = unpack2(acc2[2][q]), u3 = unpack2(acc2[3][q]);
        int f = f0 + 2 * q;
        float bv0 = bias[f], bv1 = bias[f + 1];
        size_t idx0 = (((size_t)(b * 32 + f) * 128) + oh) * 128 + owb;
        size_t idx1 = idx0 + (size_t)128 * 128;
        float4 r0 = { u0.x + bv0, u1.x + bv0, u2.x + bv0, u3.x + bv0 };
        float4 r1 = { u0.y + bv1, u1.y + bv1, u2.y + bv1, u3.y + bv1 };
        *(float4*)(out + idx0) = r0;
        *(float4*)(out + idx1) = r1;
    }
}

// ---------------------------------------------------------------------------
// S=2 3x3 conv (round-10 proven)
// ---------------------------------------------------------------------------
template<int IH>
__global__ void conv3s2_kernel(const float* __restrict__ in,
                               const float* __restrict__ w,
                               const float* __restrict__ bias,
                               const float* __restrict__ mean,
                               const float* __restrict__ rstd,
                               const float* __restrict__ add,
                               float* __restrict__ out)
{
    constexpr int IW = IH;
    constexpr int OH = IH / 2;
    constexpr int OW = OH;
    constexpr int ITH = 33, ITW = 33, ITWP = 35;
    constexpr int CHUNK = 8;
    constexpr int NCHUNK = 4;

    extern __shared__ float sm[];
    float* s_w = sm;
    float* s_in = sm + 9216;
    __shared__ float s_m[32], s_r[32];

    int b = blockIdx.z;
    int oh0 = blockIdx.y * 16, ow0 = blockIdx.x * 16;
    int tid = threadIdx.x;

    for (int i = tid; i < 9216; i += 256) {
        int f = i / 288, ck = i - f * 288;
        s_w[ck * 32 + f] = w[i];
    }
    if (tid < 32) { s_m[tid] = mean[b * 32 + tid]; s_r[tid] = rstd[b * 32 + tid]; }

    const int fg = tid >> 6;
    const int pg = tid & 63;
    const int prow = pg >> 2;
    const int pc0 = (pg & 3) * 4;
    const int f0 = fg * 8;

    u64 acc2[4][4];
    #pragma unroll
    for (int p = 0; p < 4; p++)
        #pragma unroll
        for (int q = 0; q < 4; q++) acc2[p][q] = 0ull;

    const int ih0 = oh0 * 2 - 1, iw0 = ow0 * 2 - 1;

    for (int chunk = 0; chunk < NCHUNK; chunk++) {
        __syncthreads();
        for (int i = tid; i < CHUNK * ITH * ITW; i += 256) {
            int ci = i / (ITH * ITW);
            int rem = i - ci * (ITH * ITW);
            int rr = rem / ITW, cc = rem - rr * ITW;
            int c = chunk * CHUNK + ci;
            int ih = ih0 + rr, iw = iw0 + cc;
            float v = 0.f;
            if ((unsigned)ih < (unsigned)IH && (unsigned)iw < (unsigned)IW) {
                float t = (in[(size_t)(b * 32 + c) * (IH * IW) + ih * IW + iw] - s_m[c]) * s_r[c];
                v = fmaxf(t, 0.f);
            }
            s_in[(ci * ITH + rr) * ITWP + cc] = v;
        }
        __syncthreads();

        #pragma unroll 1
        for (int ci = 0; ci < CHUNK; ci++) {
            const float* wbase = s_w + ((chunk * CHUNK + ci) * 9) * 32 + f0;
            #pragma unroll
            for (int kh = 0; kh < 3; kh++) {
                const float* rowp = s_in + (ci * ITH + prow * 2 + kh) * ITWP + pc0 * 2;
                u64 rv2[9];
                #pragma unroll
                for (int i = 0; i < 9; i++) rv2[i] = pack2(rowp[i]);
                #pragma unroll
                for (int kw = 0; kw < 3; kw++) {
                    const u64* wp = (const u64*)(wbase + (kh * 3 + kw) * 32);
                    u64 w0 = wp[0], w1 = wp[1], w2 = wp[2], w3 = wp[3];
                    #pragma unroll
                    for (int p = 0; p < 4; p++) {
                        u64 vv = rv2[p * 2 + kw];
                        fma2(acc2[p][0], vv, w0);
                        fma2(acc2[p][1], vv, w1);
                        fma2(acc2[p][2], vv, w2);
                        fma2(acc2[p][3], vv, w3);
                    }
                }
            }
        }
    }

    int oh = oh0 + prow;
    int owb = ow0 + pc0;
    #pragma unroll
    for (int q = 0; q < 4; q++) {
        float2 u0 = unpack2(acc2[0][q]), u1 = unpack2(acc2[1][q]);
        float2 u2 = unpack2(acc2[2][q]), u3 = unpack2(acc2[3][q]);
        int f = f0 + 2 * q;
        float bv0 = bias[f], bv1 = bias[f + 1];
        size_t idx0 = (((size_t)(b * 32 + f) * OH) + oh) * OW + owb;
        size_t idx1 = idx0 + (size_t)OH * OW;
        float4 r0 = { u0.x + bv0, u1.x + bv0, u2.x + bv0, u3.x + bv0 };
        float4 r1 = { u0.y + bv1, u1.y + bv1, u2.y + bv1, u3.y + bv1 };
        if (add) {
            float4 a0 = *(const float4*)(add + idx0);
            float4 a1 = *(const float4*)(add + idx1);
            r0.x += a0.x; r0.y += a0.y; r0.z += a0.z; r0.w += a0.w;
            r1.x += a1.x; r1.y += a1.y; r1.z += a1.z; r1.w += a1.w;
        }
        *(float4*)(out + idx0) = r0;
        *(float4*)(out + idx1) = r1;
    }
}

// ---------------------------------------------------------------------------
// S=1 3x3 conv via warp-level mma.sync tf32 (3-term hi/lo split).
// CTA tile: 8 output rows x 16 cols = 128 px, 32 cout.
// warp w = output row w; fragment row = pixel x (0..15).
// A smem: channel-major planes [c][r(10)][x(18)], plane stride 200 words
//   (200 mod 32 == 8 -> a-frag LDS conflict-free: (8*t4+g) distinct).
// B smem: [tap][c][f ^ ((c&3)*8)], 32 words per c row -> conflict-free.
// Phases: A_hi*B_hi ; A_lo*B_hi (rebuild A only) ; A_hi*B_lo (rebuild A,B).
// Smem = (6400 + 9216) * 4 = 62464 B -> 3 CTAs/SM.
// ---------------------------------------------------------------------------
#define S1_SMEM ((6400 + 9216) * 4)

template<int IH>
__global__ void __launch_bounds__(256)
conv3s1_mma_kernel(const float* __restrict__ in,
                   const float* __restrict__ w,
                   const float* __restrict__ bias,
                   const float* __restrict__ mean,
                   const float* __restrict__ rstd,
                   const float* __restrict__ add,
                   float* __restrict__ out)
{
    constexpr int IW = IH, OH = IH, OW = IH;
    extern __shared__ uint32_t smu[];
    uint32_t* sa = smu;            // 6400 words
    uint32_t* sb = smu + 6400;     // 9216 words
    __shared__ float s_m[32], s_r[32];

    int tid = threadIdx.x;
    int warp = tid >> 5, lane = tid & 31;
    int g = lane >> 2, t4 = lane & 3;
    int b = blockIdx.z;
    int oh0 = blockIdx.y * 8, ow0 = blockIdx.x * 16;

    if (tid < 32) { s_m[tid] = mean[b * 32 + tid]; s_r[tid] = rstd[b * 32 + tid]; }
    __syncthreads();

    const float* xin = in + (size_t)b * 32 * IH * IW;

    auto build_A = [&](bool lo) {
        for (int i = tid; i < 5760; i += 256) {
            int c = i / 180;
            int rem = i - c * 180;
            int r = rem / 18;
            int x = rem - r * 18;
            int ih = oh0 + r - 1, iw = ow0 + x - 1;
            float v = 0.f;
            if ((unsigned)ih < (unsigned)IH && (unsigned)iw < (unsigned)IW) {
                float t = (xin[(size_t)c * (IH * IW) + ih * IW + iw] - s_m[c]) * s_r[c];
                v = fmaxf(t, 0.f);
            }
            uint32_t hv = f2tf32(v);
            uint32_t sv = lo ? f2tf32(v - __uint_as_float(hv)) : hv;
            sa[c * 200 + r * 18 + x] = sv;
        }
    };
    auto build_B = [&](bool lo) {
        for (int i = tid; i < 9216; i += 256) {
            int k = i / 1024;
            int idx = i - k * 1024;
            int c = idx >> 5, f = idx & 31;
            float wv = w[(size_t)f * 288 + c * 9 + k];
            uint32_t hv = f2tf32(wv);
            uint32_t sv = lo ? f2tf32(wv - __uint_as_float(hv)) : hv;
            sb[k * 1024 + c * 32 + (f ^ ((c & 3) << 3))] = sv;
        }
    };

    float d[4][4];
    #pragma unroll
    for (int j = 0; j < 4; j++)
        #pragma unroll
        for (int q = 0; q < 4; q++) d[j][q] = 0.f;

    auto sweep = [&]() {
        #pragma unroll 1
        for (int k = 0; k < 9; k++) {
            int kh = k / 3, kw = k - kh * 3;
            const uint32_t* abase = sa + (warp + kh) * 18 + g + kw;
            const uint32_t* bbase = sb + k * 1024;
            #pragma unroll
            for (int c0 = 0; c0 < 32; c0 += 8) {
                uint32_t a[4];
                a[0] = abase[(c0 + t4) * 200];
                a[1] = abase[(c0 + t4) * 200 + 8];
                a[2] = abase[(c0 + t4 + 4) * 200];
                a[3] = abase[(c0 + t4 + 4) * 200 + 8];
                #pragma unroll
                for (int j = 0; j < 4; j++) {
                    uint32_t fcol = (uint32_t)((j * 8 + g) ^ (t4 << 3));
                    uint32_t b0 = bbase[(c0 + t4) * 32 + fcol];
                    uint32_t b1 = bbase[(c0 + t4 + 4) * 32 + fcol];
                    mma_tf32(d[j], a, b0, b1);
                }
            }
        }
    };

    // phase 1: A_hi * B_hi
    build_A(false);
    build_B(false);
    __syncthreads();
    sweep();
    __syncthreads();
    // phase 2: A_lo * B_hi
    build_A(true);
    __syncthreads();
    sweep();
    __syncthreads();
    // phase 3: A_hi * B_lo
    build_A(false);
    build_B(true);
    __syncthreads();
    sweep();

    // epilogue: d[j][0]=(px g, f), d[j][1]=(px g, f+1), d[j][2]=(px g+8, f), d[j][3]=(px g+8, f+1)
    int oh = oh0 + warp;
    #pragma unroll
    for (int j = 0; j < 4; j++) {
        int f = j * 8 + 2 * t4;
        float bv0 = bias[f], bv1 = bias[f + 1];
        size_t base0 = ((size_t)(b * 32 + f) * OH + oh) * OW + ow0;
        size_t base1 = base0 + (size_t)OH * OW;
        float v00 = d[j][0] + bv0;
        float v01 = d[j][1] + bv1;
        float v10 = d[j][2] + bv0;
        float v11 = d[j][3] + bv1;
        if (add) {
            v00 += add[base0 + g];
            v01 += add[base1 + g];
            v10 += add[base0 + g + 8];
            v11 += add[base1 + g + 8];
        }
        out[base0 + g]     = v00;
        out[base1 + g]     = v01;
        out[base0 + g + 8] = v10;
        out[base1 + g + 8] = v11;
    }
}

// ---------------------------------------------------------------------------
// 1x1 stride-2 skip projection
// ---------------------------------------------------------------------------
template<int IH>
__global__ void skip1x1_kernel(const float* __restrict__ in,
                               const float* __restrict__ w,
                               const float* __restrict__ bias,
                               float* __restrict__ out)
{
    constexpr int IW = IH;
    constexpr int OH = IH / 2;
    constexpr int OW = OH;
    __shared__ __align__(16) float s_w[32 * 32];
    int b = blockIdx.z;
    int oh0 = blockIdx.y * 16, ow0 = blockIdx.x * 16;
    int tid = threadIdx.x;
    for (int i = tid; i < 1024; i += 256) {
        int f = i >> 5, c = i & 31;
        s_w[c * 32 + f] = w[i];
    }
    __syncthreads();
    int ty = tid >> 4, tx = tid & 15;
    int oh = oh0 + ty, ow = ow0 + tx;
    int ih = oh * 2, iw = ow * 2;
    u64 acc2[16];
    #pragma unroll
    for (int q = 0; q < 16; q++) acc2[q] = 0ull;
    #pragma unroll 4
    for (int c = 0; c < 32; c++) {
        u64 vv = pack2(in[((size_t)(b * 32 + c) * IH + ih) * IW + iw]);
        const u64* wp = (const u64*)(s_w + c * 32);
        #pragma unroll
        for (int q = 0; q < 16; q++) fma2(acc2[q], vv, wp[q]);
    }
    #pragma unroll
    for (int q = 0; q < 16; q++) {
        float2 u = unpack2(acc2[q]);
        int f = 2 * q;
        out[((size_t)(b * 32 + f) * OH + oh) * OW + ow]     = u.x + bias[f];
        out[((size_t)(b * 32 + f + 1) * OH + oh) * OW + ow] = u.y + bias[f + 1];
    }
}

// ---------------------------------------------------------------------------
// Fused attention + final linear
// ---------------------------------------------------------------------------
__global__ void attn_kernel(const float* __restrict__ feat,
                            const float* __restrict__ text,
                            const float* __restrict__ attn_w,
                            const float* __restrict__ attn_b,
                            const float* __restrict__ final_w,
                            const float* __restrict__ final_b,
                            float* __restrict__ out)
{
    __shared__ __align__(16) float s_feat[32 * 256];
    __shared__ __align__(16) float s_text[256];
    __shared__ __align__(16) float s_a[5 * 256];
    __shared__ __align__(16) float s_probs[5 * 32];
    __shared__ __align__(16) float s_amap[5 * 256];

    int b = blockIdx.x;
    int tid = threadIdx.x;
    int warp = tid >> 5, lane = tid & 31;

    {
        const float4* fp = (const float4*)(feat + (size_t)b * 8192);
        float4* sp = (float4*)s_feat;
        for (int i = tid; i < 2048; i += 256) sp[i] = fp[i];
        s_text[tid] = text[b * 256 + tid];
    }
    __syncthreads();

    const float4* st4 = (const float4*)s_text;
    for (int row = warp; row < 1280; row += 8) {
        const float4* wr = (const float4*)(attn_w + (size_t)row * 256);
        float s = 0.f;
        #pragma unroll
        for (int t4 = lane; t4 < 64; t4 += 32) {
            float4 wv = wr[t4];
            float4 tv = st4[t4];
            s += wv.x * tv.x + wv.y * tv.y + wv.z * tv.z + wv.w * tv.w;
        }
        #pragma unroll
        for (int o = 16; o; o >>= 1) s += __shfl_down_sync(0xffffffffu, s, o);
        if (lane == 0) {
            float v = s + attn_b[row];
            s_a[row] = 1.f / (1.f + expf(-v));
        }
    }
    __syncthreads();

    for (int row = warp; row < 160; row += 8) {
        int h = row >> 5, c = row & 31;
        float s = 0.f;
        for (int ij = lane; ij < 256; ij += 32)
            s += s_a[h * 256 + ij] * s_feat[c * 256 + ij];
        #pragma unroll
        for (int o = 16; o; o >>= 1) s += __shfl_down_sync(0xffffffffu, s, o);
        if (lane == 0) s_probs[row] = s;
    }
    __syncthreads();

    if (warp < 5) {
        float v = s_probs[warp * 32 + lane];
        float mx = v;
        #pragma unroll
        for (int o = 16; o; o >>= 1) mx = fmaxf(mx, __shfl_xor_sync(0xffffffffu, mx, o));
        float e = expf(v - mx);
        float sum = e;
        #pragma unroll
        for (int o = 16; o; o >>= 1) sum += __shfl_xor_sync(0xffffffffu, sum, o);
        s_probs[warp * 32 + lane] = e / sum;
    }
    __syncthreads();

    for (int i = tid; i < 1280; i += 256) {
        int h = i >> 8, ij = i & 255;
        float s = 0.f;
        #pragma unroll
        for (int c = 0; c < 32; c++)
            s += s_probs[h * 32 + c] * s_feat[c * 256 + ij];
        s_amap[i] = s;
    }
    __syncthreads();

    const float4* am4 = (const float4*)s_amap;
    for (int row = warp; row < 512; row += 8) {
        const float4* wr = (const float4*)(final_w + (size_t)row * 1280);
        float s = 0.f;
        #pragma unroll
        for (int k4 = lane; k4 < 320; k4 += 32) {
            float4 wv = wr[k4];
            float4 av = am4[k4];
            s += wv.x * av.x + wv.y * av.y + wv.z * av.z + wv.w * av.w;
        }
        #pragma unroll
        for (int o = 16; o; o >>= 1) s += __shfl_down_sync(0xffffffffu, s, o);
        if (lane == 0) out[b * 512 + row] = s + final_b[row];
    }
}

// ---------------------------------------------------------------------------
// Host launch
// ---------------------------------------------------------------------------
extern "C" void kernel_launch(void* const* d_in, const int* in_sizes, int n_in,
                              void* d_out, int out_size)
{
    (void)in_sizes; (void)n_in; (void)out_size;
    const float* x       = (const float*)d_in[0];
    const float* text    = (const float*)d_in[1];
    const float* conv1_w = (const float*)d_in[2];
    const float* conv1_b = (const float*)d_in[3];
    const float* rbs_w1  = (const float*)d_in[4];
    const float* rbs_b1  = (const float*)d_in[5];
    const float* rbs_w2  = (const float*)d_in[6];
    const float* rbs_b2  = (const float*)d_in[7];
    const float* rbs_ws  = (const float*)d_in[8];
    const float* rbs_bs  = (const float*)d_in[9];
    const float* rb_w1   = (const float*)d_in[10];
    const float* rb_b1   = (const float*)d_in[11];
    const float* rb_w2   = (const float*)d_in[12];
    const float* rb_b2   = (const float*)d_in[13];
    const float* attn_w  = (const float*)d_in[14];
    const float* attn_b  = (const float*)d_in[15];
    const float* final_w = (const float*)d_in[16];
    const float* final_b = (const float*)d_in[17];
    float* out = (float*)d_out;

    float *f128, *bufA, *bufB, *bufC, *bufD, *mean, *rstd;
    cudaGetSymbolAddress((void**)&f128, g_f128);
    cudaGetSymbolAddress((void**)&bufA, g_bufA);
    cudaGetSymbolAddress((void**)&bufB, g_bufB);
    cudaGetSymbolAddress((void**)&bufC, g_bufC);
    cudaGetSymbolAddress((void**)&bufD, g_bufD);
    cudaGetSymbolAddress((void**)&mean, g_mean);
    cudaGetSymbolAddress((void**)&rstd, g_rstd);

    const int SM2 = (9216 + 8 * 33 * 35) * 4;
    cudaFuncSetAttribute(conv3s2_kernel<128>, cudaFuncAttributeMaxDynamicSharedMemorySize, SM2);
    cudaFuncSetAttribute(conv3s2_kernel<64>,  cudaFuncAttributeMaxDynamicSharedMemorySize, SM2);
    cudaFuncSetAttribute(conv3s2_kernel<32>,  cudaFuncAttributeMaxDynamicSharedMemorySize, SM2);
    cudaFuncSetAttribute(conv3s1_mma_kernel<64>, cudaFuncAttributeMaxDynamicSharedMemorySize, S1_SMEM);
    cudaFuncSetAttribute(conv3s1_mma_kernel<32>, cudaFuncAttributeMaxDynamicSharedMemorySize, S1_SMEM);
    cudaFuncSetAttribute(conv3s1_mma_kernel<16>, cudaFuncAttributeMaxDynamicSharedMemorySize, S1_SMEM);

    in_stats_kernel<<<B * 3, 256>>>(x, 256 * 256, mean, rstd);
    conv1_kernel<<<dim3(8, 8, B), 256>>>(x, conv1_w, conv1_b, mean, rstd, f128);

    in_stats_kernel<<<B * F, 256>>>(f128, 128 * 128, mean, rstd);
    conv3s2_kernel<128><<<dim3(4, 4, B), 256, SM2>>>(f128, rbs_w1, rbs_b1, mean, rstd, nullptr, bufA);
    skip1x1_kernel<128><<<dim3(4, 4, B), 256>>>(f128, rbs_ws, rbs_bs, bufB);
    in_stats_kernel<<<B * F, 256>>>(bufA, 64 * 64, mean, rstd);
    conv3s1_mma_kernel<64><<<dim3(4, 8, B), 256, S1_SMEM>>>(bufA, rbs_w2, rbs_b2, mean, rstd, bufB, bufC);

    in_stats_kernel<<<B * F, 256>>>(bufC, 64 * 64, mean, rstd);
    conv3s1_mma_kernel<64><<<dim3(4, 8, B), 256, S1_SMEM>>>(bufC, rb_w1, rb_b1, mean, rstd, nullptr, bufA);
    in_stats_kernel<<<B * F, 256>>>(bufA, 64 * 64, mean, rstd);
    conv3s1_mma_kernel<64><<<dim3(4, 8, B), 256, S1_SMEM>>>(bufA, rb_w2, rb_b2, mean, rstd, bufC, bufB);

    in_stats_kernel<<<B * F, 256>>>(bufB, 64 * 64, mean, rstd);
    conv3s2_kernel<64><<<dim3(2, 2, B), 256, SM2>>>(bufB, rbs_w1 + 9216, rbs_b1 + 32, mean, rstd, nullptr, bufA);
    skip1x1_kernel<64><<<dim3(2, 2, B), 256>>>(bufB, rbs_ws + 1024, rbs_bs + 32, bufC);
    in_stats_kernel<<<B * F, 256>>>(bufA, 32 * 32, mean, rstd);
    conv3s1_mma_kernel<32><<<dim3(2, 4, B), 256, S1_SMEM>>>(bufA, rbs_w2 + 9216, rbs_b2 + 32, mean, rstd, bufC, bufD);

    in_stats_kernel<<<B * F, 256>>>(bufD, 32 * 32, mean, rstd);
    conv3s1_mma_kernel<32><<<dim3(2, 4, B), 256, S1_SMEM>>>(bufD, rb_w1 + 9216, rb_b1 + 32, mean, rstd, nullptr, bufA);
    in_stats_kernel<<<B * F, 256>>>(bufA, 32 * 32, mean, rstd);
    conv3s1_mma_kernel<32><<<dim3(2, 4, B), 256, S1_SMEM>>>(bufA, rb_w2 + 9216, rb_b2 + 32, mean, rstd, bufD, bufB);

    in_stats_kernel<<<B * F, 256>>>(bufB, 32 * 32, mean, rstd);
    conv3s2_kernel<32><<<dim3(1, 1, B), 256, SM2>>>(bufB, rbs_w1 + 18432, rbs_b1 + 64, mean, rstd, nullptr, bufA);
    skip1x1_kernel<32><<<dim3(1, 1, B), 256>>>(bufB, rbs_ws + 2048, rbs_bs + 64, bufC);
    in_stats_kernel<<<B * F, 256>>>(bufA, 16 * 16, mean, rstd);
    conv3s1_mma_kernel<16><<<dim3(1, 2, B), 256, S1_SMEM>>>(bufA, rbs_w2 + 18432, rbs_b2 + 64, mean, rstd, bufC, bufD);

    attn_kernel<<<B, 256>>>(bufD, text, attn_w, attn_b, final_w, final_b, out);
}

// round 17
// speedup vs baseline: 1.3518x; 1.3518x over previous
#include <cuda_runtime.h>
#include <cuda_bf16.h>
#include <math.h>

#define B 64
#define F 32

typedef unsigned long long u64;

__device__ __align__(128) float g_f128[(size_t)B * F * 128 * 128];
__device__ __align__(128) float g_bufA[(size_t)B * F * 64 * 64];
__device__ __align__(128) float g_bufB[(size_t)B * F * 64 * 64];
__device__ __align__(128) float g_bufC[(size_t)B * F * 64 * 64];
__device__ __align__(128) float g_bufD[(size_t)B * F * 64 * 64];
// 12 stat slots; slot s: sums at [s*4096 .. +2048), sumsq at [s*4096+2048 .. +4096)
__device__ float g_stats[12 * 4096];

// ---------------------------------------------------------------------------
// Packed f32x2 helpers
// ---------------------------------------------------------------------------
__device__ __forceinline__ u64 pack2(float v) {
    u64 r; asm("mov.b64 %0, {%1, %1};" : "=l"(r) : "f"(v)); return r;
}
__device__ __forceinline__ void fma2(u64& acc, u64 a, u64 b) {
    asm("fma.rn.f32x2 %0, %1, %2, %0;" : "+l"(acc) : "l"(a), "l"(b));
}
__device__ __forceinline__ float2 unpack2(u64 v) {
    float2 r; asm("mov.b64 {%0, %1}, %2;" : "=f"(r.x), "=f"(r.y) : "l"(v)); return r;
}

// ---------------------------------------------------------------------------
// Input stats (x only): writes raw sum / sumsq into a stat slot
// ---------------------------------------------------------------------------
__global__ void in_stats_kernel(const float* __restrict__ in, int HW,
                                float* __restrict__ stat_out)
{
    int bc = blockIdx.x;
    const float4* p = (const float4*)(in + (size_t)bc * HW);
    int n4 = HW >> 2;
    float s1 = 0.f, s2 = 0.f;
    for (int i = threadIdx.x; i < n4; i += blockDim.x) {
        float4 v = p[i];
        s1 += v.x + v.y + v.z + v.w;
        s2 += v.x * v.x + v.y * v.y + v.z * v.z + v.w * v.w;
    }
    __shared__ float sh1[32], sh2[32];
    #pragma unroll
    for (int o = 16; o; o >>= 1) {
        s1 += __shfl_down_sync(0xffffffffu, s1, o);
        s2 += __shfl_down_sync(0xffffffffu, s2, o);
    }
    int lane = threadIdx.x & 31, w = threadIdx.x >> 5;
    if (lane == 0) { sh1[w] = s1; sh2[w] = s2; }
    __syncthreads();
    if (w == 0) {
        int nw = blockDim.x >> 5;
        s1 = lane < nw ? sh1[lane] : 0.f;
        s2 = lane < nw ? sh2[lane] : 0.f;
        #pragma unroll
        for (int o = 16; o; o >>= 1) {
            s1 += __shfl_down_sync(0xffffffffu, s1, o);
            s2 += __shfl_down_sync(0xffffffffu, s2, o);
        }
        if (lane == 0) { stat_out[bc] = s1; stat_out[2048 + bc] = s2; }
    }
}

// ---------------------------------------------------------------------------
// conv1: 7x7 s2 p3, Cin=3 (IN from stat slot), Cout=32; accumulates out stats.
// ---------------------------------------------------------------------------
__global__ void conv1_kernel(const float* __restrict__ x,
                             const float* __restrict__ w,
                             const float* __restrict__ bias,
                             const float* __restrict__ stat_in,
                             float* __restrict__ stat_out,
                             float* __restrict__ out)
{
    __shared__ __align__(16) float s_w[147][32];
    __shared__ __align__(16) float s_in[3][37][38];
    int b = blockIdx.z;
    int oh0 = blockIdx.y * 16, ow0 = blockIdx.x * 16;
    int tid = threadIdx.x;
    int lane = tid & 31;

    for (int i = tid; i < 32 * 147; i += 256) {
        int f = i / 147, ck = i - f * 147;
        s_w[ck][f] = w[i];
    }
    int ih0 = oh0 * 2 - 3, iw0 = ow0 * 2 - 3;
    const float inv_hw = 1.f / 65536.f;
    for (int c = 0; c < 3; c++) {
        int bc = b * 3 + c;
        float m = stat_in[bc] * inv_hw;
        float r = rsqrtf(stat_in[2048 + bc] * inv_hw - m * m + 1e-5f);
        const float* xp = x + (size_t)bc * 65536;
        for (int i = tid; i < 37 * 37; i += 256) {
            int rr = i / 37, cc = i - rr * 37;
            int ih = ih0 + rr, iw = iw0 + cc;
            float v = 0.f;
            if ((unsigned)ih < 256u && (unsigned)iw < 256u)
                v = (xp[ih * 256 + iw] - m) * r;
            s_in[c][rr][cc] = v;
        }
    }
    __syncthreads();

    const int fg = tid >> 6;
    const int pg = tid & 63;
    const int prow = pg >> 2;
    const int pc0 = (pg & 3) * 4;
    const int f0 = fg * 8;

    u64 acc2[4][4];
    #pragma unroll
    for (int p = 0; p < 4; p++)
        #pragma unroll
        for (int q = 0; q < 4; q++) acc2[p][q] = 0ull;

    for (int c = 0; c < 3; c++) {
        #pragma unroll 1
        for (int kh = 0; kh < 7; kh++) {
            const float* rowp = &s_in[c][prow * 2 + kh][pc0 * 2];
            u64 rv2[13];
            #pragma unroll
            for (int i = 0; i < 13; i++) rv2[i] = pack2(rowp[i]);
            #pragma unroll
            for (int kw = 0; kw < 7; kw++) {
                const u64* wp = (const u64*)&s_w[c * 49 + kh * 7 + kw][f0];
                u64 w0 = wp[0], w1 = wp[1], w2 = wp[2], w3 = wp[3];
                #pragma unroll
                for (int p = 0; p < 4; p++) {
                    u64 vv = rv2[2 * p + kw];
                    fma2(acc2[p][0], vv, w0);
                    fma2(acc2[p][1], vv, w1);
                    fma2(acc2[p][2], vv, w2);
                    fma2(acc2[p][3], vv, w3);
                }
            }
        }
    }
    int oh = oh0 + prow;
    int owb = ow0 + pc0;
    float ps[8], pq[8];
    #pragma unroll
    for (int q = 0; q < 4; q++) {
        float2 u0 = unpack2(acc2[0][q]), u1 = unpack2(acc2[1][q]);
        float2 u2 = unpack2(acc2[2][q]), u3 = unpack2(acc2[3][q]);
        int f = f0 + 2 * q;
        float bv0 = bias[f], bv1 = bias[f + 1];
        size_t idx0 = (((size_t)(b * 32 + f) * 128) + oh) * 128 + owb;
        size_t idx1 = idx0 + (size_t)128 * 128;
        float4 r0 = { u0.x + bv0, u1.x + bv0, u2.x + bv0, u3.x + bv0 };
        float4 r1 = { u0.y + bv1, u1.y + bv1, u2.y + bv1, u3.y + bv1 };
        *(float4*)(out + idx0) = r0;
        *(float4*)(out + idx1) = r1;
        ps[2 * q]     = r0.x + r0.y + r0.z + r0.w;
        pq[2 * q]     = r0.x * r0.x + r0.y * r0.y + r0.z * r0.z + r0.w * r0.w;
        ps[2 * q + 1] = r1.x + r1.y + r1.z + r1.w;
        pq[2 * q + 1] = r1.x * r1.x + r1.y * r1.y + r1.z * r1.z + r1.w * r1.w;
    }
    #pragma unroll
    for (int j = 0; j < 8; j++) {
        #pragma unroll
        for (int o = 16; o; o >>= 1) {
            ps[j] += __shfl_down_sync(0xffffffffu, ps[j], o);
            pq[j] += __shfl_down_sync(0xffffffffu, pq[j], o);
        }
    }
    if (lane == 0) {
        #pragma unroll
        for (int j = 0; j < 8; j++) {
            atomicAdd(&stat_out[b * 32 + f0 + j], ps[j]);
            atomicAdd(&stat_out[2048 + b * 32 + f0 + j], pq[j]);
        }
    }
}

// ---------------------------------------------------------------------------
// 3x3 conv, 32->32, stride S, IN+ReLU fused on load (stats from slot),
// optional residual add; accumulates output stats into stat_out slot.
// Round-10 proven compute core (FFMA2, 4px x 8f, CHUNK=8).
// ---------------------------------------------------------------------------
template<int S, int IH>
__global__ void conv3_kernel(const float* __restrict__ in,
                             const float* __restrict__ w,
                             const float* __restrict__ bias,
                             const float* __restrict__ stat_in,
                             float* __restrict__ stat_out,
                             const float* __restrict__ add,
                             float* __restrict__ out)
{
    constexpr int IW = IH;
    constexpr int OH = IH / S;
    constexpr int OW = OH;
    constexpr int ITH = 16 * S + (3 - S);
    constexpr int ITW = ITH;
    constexpr int ITWP = ITW + (S == 2 ? 2 : 1);
    constexpr int CHUNK = 8;
    constexpr int NCHUNK = 4;
    constexpr int RVN = 3 + 3 * S;

    extern __shared__ float sm[];
    float* s_w = sm;
    float* s_in = sm + 9216;
    __shared__ float s_m[32], s_r[32];

    int b = blockIdx.z;
    int oh0 = blockIdx.y * 16, ow0 = blockIdx.x * 16;
    int tid = threadIdx.x;
    int lane = tid & 31;

    for (int i = tid; i < 9216; i += 256) {
        int f = i / 288, ck = i - f * 288;
        s_w[ck * 32 + f] = w[i];
    }
    if (tid < 32) {
        const float inv_hw = 1.f / (float)(IH * IW);
        float s1 = stat_in[b * 32 + tid];
        float s2 = stat_in[2048 + b * 32 + tid];
        float m = s1 * inv_hw;
        s_m[tid] = m;
        s_r[tid] = rsqrtf(s2 * inv_hw - m * m + 1e-5f);
    }

    const int fg = tid >> 6;
    const int pg = tid & 63;
    const int prow = pg >> 2;
    const int pc0 = (pg & 3) * 4;
    const int f0 = fg * 8;

    u64 acc2[4][4];
    #pragma unroll
    for (int p = 0; p < 4; p++)
        #pragma unroll
        for (int q = 0; q < 4; q++) acc2[p][q] = 0ull;

    const int ih0 = oh0 * S - 1, iw0 = ow0 * S - 1;

    for (int chunk = 0; chunk < NCHUNK; chunk++) {
        __syncthreads();
        for (int i = tid; i < CHUNK * ITH * ITW; i += 256) {
            int ci = i / (ITH * ITW);
            int rem = i - ci * (ITH * ITW);
            int rr = rem / ITW, cc = rem - rr * ITW;
            int c = chunk * CHUNK + ci;
            int ih = ih0 + rr, iw = iw0 + cc;
            float v = 0.f;
            if ((unsigned)ih < (unsigned)IH && (unsigned)iw < (unsigned)IW) {
                float t = (in[(size_t)(b * 32 + c) * (IH * IW) + ih * IW + iw] - s_m[c]) * s_r[c];
                v = fmaxf(t, 0.f);
            }
            s_in[(ci * ITH + rr) * ITWP + cc] = v;
        }
        __syncthreads();

        #pragma unroll 1
        for (int ci = 0; ci < CHUNK; ci++) {
            const float* wbase = s_w + ((chunk * CHUNK + ci) * 9) * 32 + f0;
            #pragma unroll
            for (int kh = 0; kh < 3; kh++) {
                const float* rowp = s_in + (ci * ITH + prow * S + kh) * ITWP + pc0 * S;
                u64 rv2[RVN];
                #pragma unroll
                for (int i = 0; i < RVN; i++) rv2[i] = pack2(rowp[i]);
                #pragma unroll
                for (int kw = 0; kw < 3; kw++) {
                    const u64* wp = (const u64*)(wbase + (kh * 3 + kw) * 32);
                    u64 w0 = wp[0], w1 = wp[1], w2 = wp[2], w3 = wp[3];
                    #pragma unroll
                    for (int p = 0; p < 4; p++) {
                        u64 vv = rv2[p * S + kw];
                        fma2(acc2[p][0], vv, w0);
                        fma2(acc2[p][1], vv, w1);
                        fma2(acc2[p][2], vv, w2);
                        fma2(acc2[p][3], vv, w3);
                    }
                }
            }
        }
    }

    int oh = oh0 + prow;
    int owb = ow0 + pc0;
    float ps[8], pq[8];
    #pragma unroll
    for (int q = 0; q < 4; q++) {
        float2 u0 = unpack2(acc2[0][q]), u1 = unpack2(acc2[1][q]);
        float2 u2 = unpack2(acc2[2][q]), u3 = unpack2(acc2[3][q]);
        int f = f0 + 2 * q;
        float bv0 = bias[f], bv1 = bias[f + 1];
        size_t idx0 = (((size_t)(b * 32 + f) * OH) + oh) * OW + owb;
        size_t idx1 = idx0 + (size_t)OH * OW;
        float4 r0 = { u0.x + bv0, u1.x + bv0, u2.x + bv0, u3.x + bv0 };
        float4 r1 = { u0.y + bv1, u1.y + bv1, u2.y + bv1, u3.y + bv1 };
        if (add) {
            float4 a0 = *(const float4*)(add + idx0);
            float4 a1 = *(const float4*)(add + idx1);
            r0.x += a0.x; r0.y += a0.y; r0.z += a0.z; r0.w += a0.w;
            r1.x += a1.x; r1.y += a1.y; r1.z += a1.z; r1.w += a1.w;
        }
        *(float4*)(out + idx0) = r0;
        *(float4*)(out + idx1) = r1;
        ps[2 * q]     = r0.x + r0.y + r0.z + r0.w;
        pq[2 * q]     = r0.x * r0.x + r0.y * r0.y + r0.z * r0.z + r0.w * r0.w;
        ps[2 * q + 1] = r1.x + r1.y + r1.z + r1.w;
        pq[2 * q + 1] = r1.x * r1.x + r1.y * r1.y + r1.z * r1.z + r1.w * r1.w;
    }
    #pragma unroll
    for (int j = 0; j < 8; j++) {
        #pragma unroll
        for (int o = 16; o; o >>= 1) {
            ps[j] += __shfl_down_sync(0xffffffffu, ps[j], o);
            pq[j] += __shfl_down_sync(0xffffffffu, pq[j], o);
        }
    }
    if (lane == 0) {
        #pragma unroll
        for (int j = 0; j < 8; j++) {
            atomicAdd(&stat_out[b * 32 + f0 + j], ps[j]);
            atomicAdd(&stat_out[2048 + b * 32 + f0 + j], pq[j]);
        }
    }
}

// ---------------------------------------------------------------------------
// 1x1 stride-2 skip projection (raw input, bias). No stats needed.
// ---------------------------------------------------------------------------
template<int IH>
__global__ void skip1x1_kernel(const float* __restrict__ in,
                               const float* __restrict__ w,
                               const float* __restrict__ bias,
                               float* __restrict__ out)
{
    constexpr int IW = IH;
    constexpr int OH = IH / 2;
    constexpr int OW = OH;
    __shared__ __align__(16) float s_w[32 * 32];
    int b = blockIdx.z;
    int oh0 = blockIdx.y * 16, ow0 = blockIdx.x * 16;
    int tid = threadIdx.x;
    for (int i = tid; i < 1024; i += 256) {
        int f = i >> 5, c = i & 31;
        s_w[c * 32 + f] = w[i];
    }
    __syncthreads();
    int ty = tid >> 4, tx = tid & 15;
    int oh = oh0 + ty, ow = ow0 + tx;
    int ih = oh * 2, iw = ow * 2;
    u64 acc2[16];
    #pragma unroll
    for (int q = 0; q < 16; q++) acc2[q] = 0ull;
    #pragma unroll 4
    for (int c = 0; c < 32; c++) {
        u64 vv = pack2(in[((size_t)(b * 32 + c) * IH + ih) * IW + iw]);
        const u64* wp = (const u64*)(s_w + c * 32);
        #pragma unroll
        for (int q = 0; q < 16; q++) fma2(acc2[q], vv, wp[q]);
    }
    #pragma unroll
    for (int q = 0; q < 16; q++) {
        float2 u = unpack2(acc2[q]);
        int f = 2 * q;
        out[((size_t)(b * 32 + f) * OH + oh) * OW + ow]     = u.x + bias[f];
        out[((size_t)(b * 32 + f + 1) * OH + oh) * OW + ow] = u.y + bias[f + 1];
    }
}

// ---------------------------------------------------------------------------
// Fused attention + final linear
// ---------------------------------------------------------------------------
__global__ void attn_kernel(const float* __restrict__ feat,
                            const float* __restrict__ text,
                            const float* __restrict__ attn_w,
                            const float* __restrict__ attn_b,
                            const float* __restrict__ final_w,
                            const float* __restrict__ final_b,
                            float* __restrict__ out)
{
    __shared__ __align__(16) float s_feat[32 * 256];
    __shared__ __align__(16) float s_text[256];
    __shared__ __align__(16) float s_a[5 * 256];
    __shared__ __align__(16) float s_probs[5 * 32];
    __shared__ __align__(16) float s_amap[5 * 256];

    int b = blockIdx.x;
    int tid = threadIdx.x;
    int warp = tid >> 5, lane = tid & 31;

    {
        const float4* fp = (const float4*)(feat + (size_t)b * 8192);
        float4* sp = (float4*)s_feat;
        for (int i = tid; i < 2048; i += 256) sp[i] = fp[i];
        s_text[tid] = text[b * 256 + tid];
    }
    __syncthreads();

    const float4* st4 = (const float4*)s_text;
    for (int row = warp; row < 1280; row += 8) {
        const float4* wr = (const float4*)(attn_w + (size_t)row * 256);
        float s = 0.f;
        #pragma unroll
        for (int t4 = lane; t4 < 64; t4 += 32) {
            float4 wv = wr[t4];
            float4 tv = st4[t4];
            s += wv.x * tv.x + wv.y * tv.y + wv.z * tv.z + wv.w * tv.w;
        }
        #pragma unroll
        for (int o = 16; o; o >>= 1) s += __shfl_down_sync(0xffffffffu, s, o);
        if (lane == 0) {
            float v = s + attn_b[row];
            s_a[row] = 1.f / (1.f + expf(-v));
        }
    }
    __syncthreads();

    for (int row = warp; row < 160; row += 8) {
        int h = row >> 5, c = row & 31;
        float s = 0.f;
        for (int ij = lane; ij < 256; ij += 32)
            s += s_a[h * 256 + ij] * s_feat[c * 256 + ij];
        #pragma unroll
        for (int o = 16; o; o >>= 1) s += __shfl_down_sync(0xffffffffu, s, o);
        if (lane == 0) s_probs[row] = s;
    }
    __syncthreads();

    if (warp < 5) {
        float v = s_probs[warp * 32 + lane];
        float mx = v;
        #pragma unroll
        for (int o = 16; o; o >>= 1) mx = fmaxf(mx, __shfl_xor_sync(0xffffffffu, mx, o));
        float e = expf(v - mx);
        float sum = e;
        #pragma unroll
        for (int o = 16; o; o >>= 1) sum += __shfl_xor_sync(0xffffffffu, sum, o);
        s_probs[warp * 32 + lane] = e / sum;
    }
    __syncthreads();

    for (int i = tid; i < 1280; i += 256) {
        int h = i >> 8, ij = i & 255;
        float s = 0.f;
        #pragma unroll
        for (int c = 0; c < 32; c++)
            s += s_probs[h * 32 + c] * s_feat[c * 256 + ij];
        s_amap[i] = s;
    }
    __syncthreads();

    const float4* am4 = (const float4*)s_amap;
    for (int row = warp; row < 512; row += 8) {
        const float4* wr = (const float4*)(final_w + (size_t)row * 1280);
        float s = 0.f;
        #pragma unroll
        for (int k4 = lane; k4 < 320; k4 += 32) {
            float4 wv = wr[k4];
            float4 av = am4[k4];
            s += wv.x * av.x + wv.y * av.y + wv.z * av.z + wv.w * av.w;
        }
        #pragma unroll
        for (int o = 16; o; o >>= 1) s += __shfl_down_sync(0xffffffffu, s, o);
        if (lane == 0) out[b * 512 + row] = s + final_b[row];
    }
}

// ---------------------------------------------------------------------------
// Host launch
// ---------------------------------------------------------------------------
extern "C" void kernel_launch(void* const* d_in, const int* in_sizes, int n_in,
                              void* d_out, int out_size)
{
    (void)in_sizes; (void)n_in; (void)out_size;
    const float* x       = (const float*)d_in[0];
    const float* text    = (const float*)d_in[1];
    const float* conv1_w = (const float*)d_in[2];
    const float* conv1_b = (const float*)d_in[3];
    const float* rbs_w1  = (const float*)d_in[4];
    const float* rbs_b1  = (const float*)d_in[5];
    const float* rbs_w2  = (const float*)d_in[6];
    const float* rbs_b2  = (const float*)d_in[7];
    const float* rbs_ws  = (const float*)d_in[8];
    const float* rbs_bs  = (const float*)d_in[9];
    const float* rb_w1   = (const float*)d_in[10];
    const float* rb_b1   = (const float*)d_in[11];
    const float* rb_w2   = (const float*)d_in[12];
    const float* rb_b2   = (const float*)d_in[13];
    const float* attn_w  = (const float*)d_in[14];
    const float* attn_b  = (const float*)d_in[15];
    const float* final_w = (const float*)d_in[16];
    const float* final_b = (const float*)d_in[17];
    float* out = (float*)d_out;

    float *f128, *bufA, *bufB, *bufC, *bufD, *st;
    cudaGetSymbolAddress((void**)&f128, g_f128);
    cudaGetSymbolAddress((void**)&bufA, g_bufA);
    cudaGetSymbolAddress((void**)&bufB, g_bufB);
    cudaGetSymbolAddress((void**)&bufC, g_bufC);
    cudaGetSymbolAddress((void**)&bufD, g_bufD);
    cudaGetSymbolAddress((void**)&st, g_stats);

    // stat slots
    float* st0  = st;            // x
    float* st1  = st + 1 * 4096; // f128
    float* st2  = st + 2 * 4096; // bufA (s2 out, 64^2)
    float* st3  = st + 3 * 4096; // bufC
    float* st4  = st + 4 * 4096; // bufA
    float* st5  = st + 5 * 4096; // bufB
    float* st6  = st + 6 * 4096; // bufA (s2 out, 32^2)
    float* st7  = st + 7 * 4096; // bufD
    float* st8  = st + 8 * 4096; // bufA
    float* st9  = st + 9 * 4096; // bufB
    float* st10 = st + 10 * 4096; // bufA (s2 out, 16^2)
    float* st11 = st + 11 * 4096; // bufD (unused)

    cudaMemsetAsync(st, 0, 12 * 4096 * sizeof(float), 0);

    const int SM1 = (9216 + 8 * 18 * 19) * 4;
    const int SM2 = (9216 + 8 * 33 * 35) * 4;
    cudaFuncSetAttribute(conv3_kernel<2, 128>, cudaFuncAttributeMaxDynamicSharedMemorySize, SM2);
    cudaFuncSetAttribute(conv3_kernel<2, 64>,  cudaFuncAttributeMaxDynamicSharedMemorySize, SM2);
    cudaFuncSetAttribute(conv3_kernel<2, 32>,  cudaFuncAttributeMaxDynamicSharedMemorySize, SM2);
    cudaFuncSetAttribute(conv3_kernel<1, 64>,  cudaFuncAttributeMaxDynamicSharedMemorySize, SM1);
    cudaFuncSetAttribute(conv3_kernel<1, 32>,  cudaFuncAttributeMaxDynamicSharedMemorySize, SM1);
    cudaFuncSetAttribute(conv3_kernel<1, 16>,  cudaFuncAttributeMaxDynamicSharedMemorySize, SM1);

    // stem: stats(x) -> conv1
    in_stats_kernel<<<B * 3, 256>>>(x, 256 * 256, st0);
    conv1_kernel<<<dim3(8, 8, B), 256>>>(x, conv1_w, conv1_b, st0, st1, f128);

    // strided block 0: 128 -> 64
    conv3_kernel<2, 128><<<dim3(4, 4, B), 256, SM2>>>(f128, rbs_w1, rbs_b1, st1, st2, nullptr, bufA);
    skip1x1_kernel<128><<<dim3(4, 4, B), 256>>>(f128, rbs_ws, rbs_bs, bufB);
    conv3_kernel<1, 64><<<dim3(4, 4, B), 256, SM1>>>(bufA, rbs_w2, rbs_b2, st2, st3, bufB, bufC);

    // plain block 0 (64x64)
    conv3_kernel<1, 64><<<dim3(4, 4, B), 256, SM1>>>(bufC, rb_w1, rb_b1, st3, st4, nullptr, bufA);
    conv3_kernel<1, 64><<<dim3(4, 4, B), 256, SM1>>>(bufA, rb_w2, rb_b2, st4, st5, bufC, bufB);

    // strided block 1: 64 -> 32
    conv3_kernel<2, 64><<<dim3(2, 2, B), 256, SM2>>>(bufB, rbs_w1 + 9216, rbs_b1 + 32, st5, st6, nullptr, bufA);
    skip1x1_kernel<64><<<dim3(2, 2, B), 256>>>(bufB, rbs_ws + 1024, rbs_bs + 32, bufC);
    conv3_kernel<1, 32><<<dim3(2, 2, B), 256, SM1>>>(bufA, rbs_w2 + 9216, rbs_b2 + 32, st6, st7, bufC, bufD);

    // plain block 1 (32x32)
    conv3_kernel<1, 32><<<dim3(2, 2, B), 256, SM1>>>(bufD, rb_w1 + 9216, rb_b1 + 32, st7, st8, nullptr, bufA);
    conv3_kernel<1, 32><<<dim3(2, 2, B), 256, SM1>>>(bufA, rb_w2 + 9216, rb_b2 + 32, st8, st9, bufD, bufB);

    // strided block 2: 32 -> 16
    conv3_kernel<2, 32><<<dim3(1, 1, B), 256, SM2>>>(bufB, rbs_w1 + 18432, rbs_b1 + 64, st9, st10, nullptr, bufA);
    skip1x1_kernel<32><<<dim3(1, 1, B), 256>>>(bufB, rbs_ws + 2048, rbs_bs + 64, bufC);
    conv3_kernel<1, 16><<<dim3(1, 1, B), 256, SM1>>>(bufA, rbs_w2 + 18432, rbs_b2 + 64, st10, st11, bufC, bufD);

    // fused attention + final projection
    attn_kernel<<<B, 256>>>(bufD, text, attn_w, attn_b, final_w, final_b, out);
}